// round 16
// baseline (speedup 1.0000x reference)
#include <cuda_runtime.h>
#include <cuda_fp16.h>
#include <cstdint>

// Problem dims
#define B_  2
#define C_  4
#define D_  64
#define H_  160
#define W_  160
#define HW_ (H_ * W_)            // 25600
#define BC_ (B_ * C_)            // 8
#define NSLICE (BC_ * D_)        // 512
#define NVOX_PER_CH (B_ * D_ * H_ * W_)  // 3,276,800

// Gaussian window (k=11, sigma=1.5), normalized, symmetric.
#define GW0 0.00102838f
#define GW1 0.00759876f
#define GW2 0.03600077f
#define GW3 0.10936069f
#define GW4 0.21300554f
#define GW5 0.26601173f

#define SSIM_C1 1.0e-4f
#define SSIM_C2 9.0e-4f

__host__ __device__ constexpr float gw(int t) {
    return t == 0 ? GW0 : t == 1 ? GW1 : t == 2 ? GW2 : t == 3 ? GW3 :
           t == 4 ? GW4 : t == 5 ? GW5 : t == 6 ? GW4 : t == 7 ? GW3 :
           t == 8 ? GW2 : t == 9 ? GW1 : GW0;
}

// fp16 scratch: (mu1,mu2), (E11,E22) as half2, E12 as half. 131 MB total.
// Storage-only fp16 (R8-proven); all arithmetic fp32.
__device__ __half2 gA[(long long)NSLICE * HW_];   // (mu1, mu2)
__device__ __half2 gB[(long long)NSLICE * HW_];   // (E11, E22)
__device__ __half  gC[(long long)NSLICE * HW_];   // E12
__device__ float   g_acc[C_];
__device__ unsigned int g_done;                   // passB completion counter

#define NBLK_B (BC_ * H_ * 2)    // 2560 passB blocks

// fp32 11-tap conv over v[J..J+10] of an N-float register array.
template <int J, int N>
__device__ __forceinline__ float convs(const float (&v)[N]) {
    float s = v[J] * GW0;
#pragma unroll
    for (int k = 1; k < 11; k++) s = fmaf(v[J + k], gw(k), s);
    return s;
}

// ---------------------------------------------------------------------------
// Pass A: x-tile 32, full-H y-sweep: 160 outputs in 4 iterations of 40.
// 50-row mid frame covering global rows 40*it-5 .. 40*it+44; between
// iterations copy the 10 carry rows (slots 40..49 -> 0..9). All smem indices
// stay frame-local / compile-time.
// Input tile: half2(x1,x2)-packed. Mids fp32. Phase 3: 10-y windows with the
// e12 field split 5/5 across warp-halves (275/275 FMA balance).
// ---------------------------------------------------------------------------
#define TSX 32
#define HALO 5
#define YIT 40    // outputs per iteration
#define NIT 4     // iterations (full H)
#define RR 50     // frame rows = YIT + 2*HALO
#define SNX 48    // input cols (j <-> gx = tx0 - 8 + j)
#define MNX 36    // mid row pad (16B-aligned)

__global__ void __launch_bounds__(256) passA_kernel(
    const float* __restrict__ img1, const float* __restrict__ img2) {
    __shared__ __half2 sp[RR][SNX];     // 9.6 KB
    __shared__ float mid[5][RR][MNX];   // 36 KB   (total 45.6 KB)

    const int slice = blockIdx.z;            // bc*D + d
    const int tx0 = blockIdx.x * TSX;
    const int tid = threadIdx.x;

    const float4* p1 = (const float4*)(img1 + (long long)slice * HW_);
    const float4* p2 = (const float4*)(img2 + (long long)slice * HW_);

#pragma unroll 1
    for (int it = 0; it < NIT; it++) {
        const int rbase = (it == 0) ? -HALO : (it * YIT + HALO);
        const int nrows = (it == 0) ? RR : YIT;
        const int msoff = (it == 0) ? 0 : (2 * HALO);

        if (it > 0) __syncthreads();  // P3(prev) done before carry-copy/mid reuse

        // Phase 1: load nrows input rows into sp slots 0..nrows-1.
        for (int i = tid; i < nrows * 12; i += 256) {
            int y = i / 12, k = i - y * 12;
            int gy = rbase + y;
            int gx0 = tx0 - 8 + 4 * k;
            float4 a = make_float4(0.f, 0.f, 0.f, 0.f);
            float4 b = a;
            if (((unsigned)gy < (unsigned)H_) && ((unsigned)gx0 < (unsigned)W_)) {
                int gi = (gy * W_ + gx0) >> 2;
                a = p1[gi];
                b = p2[gi];
            }
            union { __half2 h[4]; uint4 u; } t;
            t.h[0] = __floats2half2_rn(a.x, b.x);
            t.h[1] = __floats2half2_rn(a.y, b.y);
            t.h[2] = __floats2half2_rn(a.z, b.z);
            t.h[3] = __floats2half2_rn(a.w, b.w);
            *(uint4*)&sp[y][4 * k] = t.u;
        }
        // Carry copy (it>0): mid slots 40..49 -> 0..9. 5 fields x 10 rows x
        // 9 float4-chunks = 450 items. Disjoint src/dst; runs alongside P1.
        if (it > 0) {
            for (int i = tid; i < 450; i += 256) {
                int f = i / 90;
                int rem = i - f * 90;
                int r = rem / 9;
                int ch = (rem - r * 9) * 4;
                *(float4*)&mid[f][r][ch] = *(const float4*)&mid[f][YIT + r][ch];
            }
        }
        __syncthreads();

        // Phase 2: W-conv of the nrows new rows -> mid slots msoff..msoff+nrows-1.
        for (int i = tid; i < nrows * 8; i += 256) {
            int y = i >> 3;
            int x0 = (i & 7) << 2;
            __half2 w[20];
#pragma unroll
            for (int k = 0; k < 5; k++)
                *(uint4*)&w[4 * k] = *(const uint4*)&sp[y][x0 + 4 * k];
            float A[14], Bv[14];
#pragma unroll
            for (int t = 0; t < 14; t++) {
                float2 f = __half22float2(w[t + 3]);
                A[t] = f.x;
                Bv[t] = f.y;
            }
            int ms = msoff + y;
            float4 r;
            r.x = convs<0>(A); r.y = convs<1>(A); r.z = convs<2>(A); r.w = convs<3>(A);
            *(float4*)&mid[0][ms][x0] = r;
            r.x = convs<0>(Bv); r.y = convs<1>(Bv); r.z = convs<2>(Bv); r.w = convs<3>(Bv);
            *(float4*)&mid[1][ms][x0] = r;
            {
                float sq[14];
#pragma unroll
                for (int t = 0; t < 14; t++) sq[t] = A[t] * A[t];
                r.x = convs<0>(sq); r.y = convs<1>(sq); r.z = convs<2>(sq); r.w = convs<3>(sq);
                *(float4*)&mid[2][ms][x0] = r;
            }
            {
                float sq[14];
#pragma unroll
                for (int t = 0; t < 14; t++) sq[t] = Bv[t] * Bv[t];
                r.x = convs<0>(sq); r.y = convs<1>(sq); r.z = convs<2>(sq); r.w = convs<3>(sq);
                *(float4*)&mid[3][ms][x0] = r;
            }
            {
                float sq[14];
#pragma unroll
                for (int t = 0; t < 14; t++) sq[t] = A[t] * Bv[t];
                r.x = convs<0>(sq); r.y = convs<1>(sq); r.z = convs<2>(sq); r.w = convs<3>(sq);
                *(float4*)&mid[4][ms][x0] = r;
            }
        }
        __syncthreads();

        // Phase 3: H-conv, 10-y windows (frame rows ylocal..ylocal+19).
        // half0: fields 0,1 -> gA, plus e12 outputs u=0..4.
        // half1: fields 2,3 -> gB, plus e12 outputs u=5..9. 275/275 FMA.
        {
            int t128 = tid & 127;
            int x = t128 & 31;
            int ylocal = (t128 >> 5) * 10;   // 0,10,20,30
            int halfsel = tid >> 7;
            int vox = slice * HW_ + (it * YIT + ylocal) * W_ + (tx0 + x);
            float v[20];
            float w15[15];
#define HCONV10(DST)                                                   \
            DST[0] = convs<0>(v); DST[1] = convs<1>(v);                \
            DST[2] = convs<2>(v); DST[3] = convs<3>(v);                \
            DST[4] = convs<4>(v); DST[5] = convs<5>(v);                \
            DST[6] = convs<6>(v); DST[7] = convs<7>(v);                \
            DST[8] = convs<8>(v); DST[9] = convs<9>(v);
            if (halfsel == 0) {
                float m1[10];
#pragma unroll
                for (int t = 0; t < 20; t++) v[t] = mid[0][ylocal + t][x];
                HCONV10(m1)
#pragma unroll
                for (int t = 0; t < 20; t++) v[t] = mid[1][ylocal + t][x];
#pragma unroll
                for (int u = 0; u < 10; u++) {
                    float m2 = u == 0 ? convs<0>(v) : u == 1 ? convs<1>(v)
                             : u == 2 ? convs<2>(v) : u == 3 ? convs<3>(v)
                             : u == 4 ? convs<4>(v) : u == 5 ? convs<5>(v)
                             : u == 6 ? convs<6>(v) : u == 7 ? convs<7>(v)
                             : u == 8 ? convs<8>(v) : convs<9>(v);
                    gA[vox + u * W_] = __floats2half2_rn(m1[u], m2);
                }
                // e12 lower half: outputs u = 0..4, window rows ylocal..ylocal+14
#pragma unroll
                for (int t = 0; t < 15; t++) w15[t] = mid[4][ylocal + t][x];
                gC[vox + 0 * W_] = __float2half_rn(convs<0>(w15));
                gC[vox + 1 * W_] = __float2half_rn(convs<1>(w15));
                gC[vox + 2 * W_] = __float2half_rn(convs<2>(w15));
                gC[vox + 3 * W_] = __float2half_rn(convs<3>(w15));
                gC[vox + 4 * W_] = __float2half_rn(convs<4>(w15));
            } else {
                float e1[10];
#pragma unroll
                for (int t = 0; t < 20; t++) v[t] = mid[2][ylocal + t][x];
                HCONV10(e1)
#pragma unroll
                for (int t = 0; t < 20; t++) v[t] = mid[3][ylocal + t][x];
#pragma unroll
                for (int u = 0; u < 10; u++) {
                    float e2 = u == 0 ? convs<0>(v) : u == 1 ? convs<1>(v)
                             : u == 2 ? convs<2>(v) : u == 3 ? convs<3>(v)
                             : u == 4 ? convs<4>(v) : u == 5 ? convs<5>(v)
                             : u == 6 ? convs<6>(v) : u == 7 ? convs<7>(v)
                             : u == 8 ? convs<8>(v) : convs<9>(v);
                    gB[vox + u * W_] = __floats2half2_rn(e1[u], e2);
                }
                // e12 upper half: outputs u = 5..9, window rows ylocal+5..ylocal+19
#pragma unroll
                for (int t = 0; t < 15; t++) w15[t] = mid[4][ylocal + 5 + t][x];
                gC[vox + 5 * W_] = __float2half_rn(convs<0>(w15));
                gC[vox + 6 * W_] = __float2half_rn(convs<1>(w15));
                gC[vox + 7 * W_] = __float2half_rn(convs<2>(w15));
                gC[vox + 8 * W_] = __float2half_rn(convs<3>(w15));
                gC[vox + 9 * W_] = __float2half_rn(convs<4>(w15));
            }
#undef HCONV10
        }
    }
}

// ---------------------------------------------------------------------------
// Pass B: D-conv via 13-deep rotating ring, D-split x2 (32 steps/half-column).
// Slot s holds real plane p with (p - dlo) mod 13 == s. At step d_rel, tap k
// is plane dlo + d_rel - 5 + k -> slot (d_rel + 8 + k) % 13; refill loads
// plane dlo + d_rel + 8 into slot (d_rel + 8) % 13.
// No occupancy cap (R14 lesson: a reg cap spills the ring).
// Last-finishing block writes the final output (completion counter).
// ---------------------------------------------------------------------------
template <int J>
__device__ __forceinline__ float conv13(const float (&r)[13]) {
    float s = r[(J + 8) % 13] * GW0;
#pragma unroll
    for (int k = 1; k < 11; k++) s = fmaf(r[(J + 8 + k) % 13], gw(k), s);
    return s;
}

template <int J>
__device__ __forceinline__ void stepJ(
    float (&a)[13], float (&b)[13], float (&c11)[13],
    float (&c22)[13], float (&c12)[13],
    const __half2* __restrict__ tA, const __half2* __restrict__ tB,
    const __half* __restrict__ tC,
    int o, float& acc, bool ld) {
    float mu1 = conv13<J>(a);
    float mu2 = conv13<J>(b);
    float e11 = conv13<J>(c11);
    float e22 = conv13<J>(c22);
    float e12 = conv13<J>(c12);

    float mu1sq = mu1 * mu1;
    float mu2sq = mu2 * mu2;
    float mu12 = mu1 * mu2;
    float s11 = e11 - mu1sq;
    float s22 = e22 - mu2sq;
    float s12 = e12 - mu12;

    float num = (2.f * mu12 + SSIM_C1) * (2.f * s12 + SSIM_C2);
    float den = (mu1sq + mu2sq + SSIM_C1) * (s11 + s22 + SSIM_C2);
    acc += __fdividef(num, den);

    constexpr int RS = (J + 8) % 13;
    if (ld) {
        float2 ab = __half22float2(tA[o]);
        float2 ee = __half22float2(tB[o]);
        a[RS] = ab.x; b[RS] = ab.y;
        c11[RS] = ee.x; c22[RS] = ee.y;
        c12[RS] = __half2float(tC[o]);
    } else {
        a[RS] = 0.f; b[RS] = 0.f; c11[RS] = 0.f; c22[RS] = 0.f; c12[RS] = 0.f;
    }
}

__global__ void __launch_bounds__(160) passB_kernel(float* __restrict__ out) {
    const int bid = blockIdx.x;          // ((bc*H + y) << 1) | dh
    const int dh = bid & 1;
    const int rest = bid >> 1;           // bc*H + y
    const int y = rest % H_;
    const int bc = rest / H_;
    const int c = bc % C_;
    const int x = threadIdx.x;           // 0..159
    const int dlo = dh << 5;             // 0 or 32

    const int colbase = (bc * D_ + dlo) * HW_ + y * W_ + x;
    const __half2* tA = gA + colbase;
    const __half2* tB = gB + colbase;
    const __half*  tC = gC + colbase;

    float a[13], b[13], c11[13], c22[13], c12[13];
    // Preload under slot = (plane - dlo) mod 13:
    //   slots 0..7  <- planes dlo .. dlo+7
    //   slots 8..12 <- planes dlo-5 .. dlo-1   (zero when plane < 0, i.e. dh==0)
#pragma unroll
    for (int k = 0; k < 13; k++) {
        const int rel = (k < 8) ? k : (k - 13);   // -5..7
        const int o = rel * HW_;
        bool ok = (dlo + rel) >= 0;               // upper bound always ok
        if (ok) {
            float2 ab = __half22float2(tA[o]);
            float2 ee = __half22float2(tB[o]);
            a[k] = ab.x; b[k] = ab.y;
            c11[k] = ee.x; c22[k] = ee.y;
            c12[k] = __half2float(tC[o]);
        } else {
            a[k] = 0.f; b[k] = 0.f; c11[k] = 0.f; c22[k] = 0.f; c12[k] = 0.f;
        }
    }

    float acc = 0.f;
    int o = 8 * HW_;  // step d_rel refills plane dlo + d_rel + 8

    // Refill validity: dlo + d_rel + 8 <= 63  <=>  d_rel <= 55 - dlo.
#define STEP(J, LD) stepJ<J>(a, b, c11, c22, c12, tA, tB, tC, o, acc, (LD)); o += HW_;

    // d_rel = 0..25 : two rotations of 13.
#pragma unroll 1
    for (int r = 0; r < 2; r++) {
        int dbase = r * 13;
        STEP(0,  dbase + 0  <= 55 - dlo)
        STEP(1,  dbase + 1  <= 55 - dlo)
        STEP(2,  dbase + 2  <= 55 - dlo)
        STEP(3,  dbase + 3  <= 55 - dlo)
        STEP(4,  dbase + 4  <= 55 - dlo)
        STEP(5,  dbase + 5  <= 55 - dlo)
        STEP(6,  dbase + 6  <= 55 - dlo)
        STEP(7,  dbase + 7  <= 55 - dlo)
        STEP(8,  dbase + 8  <= 55 - dlo)
        STEP(9,  dbase + 9  <= 55 - dlo)
        STEP(10, dbase + 10 <= 55 - dlo)
        STEP(11, dbase + 11 <= 55 - dlo)
        STEP(12, dbase + 12 <= 55 - dlo)
    }
    // d_rel = 26..31 (J = 0..5): load valid only for dh == 0 (planes 34..39).
    {
        const bool lt = (dlo == 0);
        STEP(0, lt) STEP(1, lt) STEP(2, lt)
        STEP(3, lt) STEP(4, lt) STEP(5, lt)
    }
#undef STEP

    __shared__ float red[5];
    __shared__ bool s_last;
#pragma unroll
    for (int off = 16; off > 0; off >>= 1)
        acc += __shfl_down_sync(0xffffffffu, acc, off);
    if ((threadIdx.x & 31) == 0) red[threadIdx.x >> 5] = acc;
    __syncthreads();
    if (threadIdx.x == 0) {
        float s = red[0] + red[1] + red[2] + red[3] + red[4];
        atomicAdd(&g_acc[c], s);
        __threadfence();
        unsigned int t = atomicAdd(&g_done, 1u);
        s_last = (t == (unsigned)(NBLK_B - 1));
    }
    __syncthreads();
    // Last block to finish: emit the final loss and reset state for the
    // next graph replay (deterministic: exactly one block takes this path).
    if (s_last) {
        if (threadIdx.x < C_) {
            float s = *((volatile float*)&g_acc[threadIdx.x]);
            out[threadIdx.x] = 1.f - s * (1.f / (float)NVOX_PER_CH);
            g_acc[threadIdx.x] = 0.f;
        }
        if (threadIdx.x == 0) g_done = 0u;
    }
}

extern "C" void kernel_launch(void* const* d_in, const int* in_sizes, int n_in,
                              void* d_out, int out_size) {
    (void)in_sizes; (void)n_in; (void)out_size;
    const float* img1 = (const float*)d_in[0];
    const float* img2 = (const float*)d_in[1];
    float* out = (float*)d_out;

    dim3 gA_(W_ / TSX, 1, NSLICE);  // (5, 1, 512)
    passA_kernel<<<gA_, 256>>>(img1, img2);
    passB_kernel<<<NBLK_B, 160>>>(out);
}

// round 17
// speedup vs baseline: 1.5039x; 1.5039x over previous
#include <cuda_runtime.h>
#include <cuda_fp16.h>
#include <cstdint>

// Problem dims
#define B_  2
#define C_  4
#define D_  64
#define H_  160
#define W_  160
#define HW_ (H_ * W_)            // 25600
#define BC_ (B_ * C_)            // 8
#define NSLICE (BC_ * D_)        // 512
#define NVOX_PER_CH (B_ * D_ * H_ * W_)  // 3,276,800

// Gaussian window (k=11, sigma=1.5), normalized, symmetric.
#define GW0 0.00102838f
#define GW1 0.00759876f
#define GW2 0.03600077f
#define GW3 0.10936069f
#define GW4 0.21300554f
#define GW5 0.26601173f

#define SSIM_C1 1.0e-4f
#define SSIM_C2 9.0e-4f

__host__ __device__ constexpr float gw(int t) {
    return t == 0 ? GW0 : t == 1 ? GW1 : t == 2 ? GW2 : t == 3 ? GW3 :
           t == 4 ? GW4 : t == 5 ? GW5 : t == 6 ? GW4 : t == 7 ? GW3 :
           t == 8 ? GW2 : t == 9 ? GW1 : GW0;
}

// fp16 scratch: (mu1,mu2), (E11,E22) as half2, E12 as half. 131 MB total.
// Storage-only fp16 (R8-proven); all arithmetic fp32.
__device__ __half2 gA[(long long)NSLICE * HW_];   // (mu1, mu2)
__device__ __half2 gB[(long long)NSLICE * HW_];   // (E11, E22)
__device__ __half  gC[(long long)NSLICE * HW_];   // E12
__device__ float   g_acc[C_];
__device__ unsigned int g_done;                   // passB completion counter

#define NBLK_B (BC_ * H_ * 2)    // 2560 passB blocks

// fp32 11-tap conv over v[J..J+10] of an N-float register array.
template <int J, int N>
__device__ __forceinline__ float convs(const float (&v)[N]) {
    float s = v[J] * GW0;
#pragma unroll
    for (int k = 1; k < 11; k++) s = fmaf(v[J + k], gw(k), s);
    return s;
}

// ---------------------------------------------------------------------------
// Pass A (exact R15 geometry/structure — measured 86-91 us twice):
// x-tile 32, y-sweep of 80 outputs in 2 iterations of 40. 50-row mid frame;
// between iterations copy the 10 carry rows (slots 40..49 -> 0..9).
// Input tile: half2(x1,x2)-packed. Mids fp32. Phase 3: 10-y sliding windows.
// ---------------------------------------------------------------------------
#define TSX 32
#define HALO 5
#define YIT 40    // outputs per iteration
#define RR 50     // frame rows = YIT + 2*HALO
#define SNX 48    // input cols (j <-> gx = tx0 - 8 + j)
#define MNX 36    // mid row pad (16B-aligned)

__global__ void __launch_bounds__(256) passA_kernel(
    const float* __restrict__ img1, const float* __restrict__ img2) {
    __shared__ __half2 sp[RR][SNX];     // 9.6 KB
    __shared__ float mid[5][RR][MNX];   // 36 KB   (total 45.6 KB)

    const int slice = blockIdx.z;            // bc*D + d
    const int ty0 = blockIdx.y * (2 * YIT);  // 0 or 80
    const int tx0 = blockIdx.x * TSX;
    const int tid = threadIdx.x;

    const float4* p1 = (const float4*)(img1 + (long long)slice * HW_);
    const float4* p2 = (const float4*)(img2 + (long long)slice * HW_);

#pragma unroll 1
    for (int it = 0; it < 2; it++) {
        const int rbase = (it == 0) ? (ty0 - HALO) : (ty0 + YIT + HALO);
        const int nrows = (it == 0) ? RR : YIT;
        const int msoff = (it == 0) ? 0 : (2 * HALO);

        if (it == 1) __syncthreads();  // P3(it0) done before carry-copy/mid reuse

        // Phase 1: load nrows input rows into sp slots 0..nrows-1.
        for (int i = tid; i < nrows * 12; i += 256) {
            int y = i / 12, k = i - y * 12;
            int gy = rbase + y;
            int gx0 = tx0 - 8 + 4 * k;
            float4 a = make_float4(0.f, 0.f, 0.f, 0.f);
            float4 b = a;
            if (((unsigned)gy < (unsigned)H_) && ((unsigned)gx0 < (unsigned)W_)) {
                int gi = (gy * W_ + gx0) >> 2;
                a = p1[gi];
                b = p2[gi];
            }
            union { __half2 h[4]; uint4 u; } t;
            t.h[0] = __floats2half2_rn(a.x, b.x);
            t.h[1] = __floats2half2_rn(a.y, b.y);
            t.h[2] = __floats2half2_rn(a.z, b.z);
            t.h[3] = __floats2half2_rn(a.w, b.w);
            *(uint4*)&sp[y][4 * k] = t.u;
        }
        // Carry copy (it==1): mid slots 40..49 -> 0..9. 5 fields x 10 rows x
        // 9 float4-chunks = 450 items. Disjoint src/dst; runs alongside P1.
        if (it == 1) {
            for (int i = tid; i < 450; i += 256) {
                int f = i / 90;
                int rem = i - f * 90;
                int r = rem / 9;
                int ch = (rem - r * 9) * 4;
                *(float4*)&mid[f][r][ch] = *(const float4*)&mid[f][YIT + r][ch];
            }
        }
        __syncthreads();

        // Phase 2: W-conv of the nrows new rows -> mid slots msoff..msoff+nrows-1.
        for (int i = tid; i < nrows * 8; i += 256) {
            int y = i >> 3;
            int x0 = (i & 7) << 2;
            __half2 w[20];
#pragma unroll
            for (int k = 0; k < 5; k++)
                *(uint4*)&w[4 * k] = *(const uint4*)&sp[y][x0 + 4 * k];
            float A[14], Bv[14];
#pragma unroll
            for (int t = 0; t < 14; t++) {
                float2 f = __half22float2(w[t + 3]);
                A[t] = f.x;
                Bv[t] = f.y;
            }
            int ms = msoff + y;
            float4 r;
            r.x = convs<0>(A); r.y = convs<1>(A); r.z = convs<2>(A); r.w = convs<3>(A);
            *(float4*)&mid[0][ms][x0] = r;
            r.x = convs<0>(Bv); r.y = convs<1>(Bv); r.z = convs<2>(Bv); r.w = convs<3>(Bv);
            *(float4*)&mid[1][ms][x0] = r;
            {
                float sq[14];
#pragma unroll
                for (int t = 0; t < 14; t++) sq[t] = A[t] * A[t];
                r.x = convs<0>(sq); r.y = convs<1>(sq); r.z = convs<2>(sq); r.w = convs<3>(sq);
                *(float4*)&mid[2][ms][x0] = r;
            }
            {
                float sq[14];
#pragma unroll
                for (int t = 0; t < 14; t++) sq[t] = Bv[t] * Bv[t];
                r.x = convs<0>(sq); r.y = convs<1>(sq); r.z = convs<2>(sq); r.w = convs<3>(sq);
                *(float4*)&mid[3][ms][x0] = r;
            }
            {
                float sq[14];
#pragma unroll
                for (int t = 0; t < 14; t++) sq[t] = A[t] * Bv[t];
                r.x = convs<0>(sq); r.y = convs<1>(sq); r.z = convs<2>(sq); r.w = convs<3>(sq);
                *(float4*)&mid[4][ms][x0] = r;
            }
        }
        __syncthreads();

        // Phase 3: H-conv, 10-y windows (20 frame rows, slots ylocal..ylocal+19).
        // Warps 0-3: fields 0,1 -> gA. Warps 4-7: fields 2,3 -> gB; 4 -> gC.
        {
            int t128 = tid & 127;
            int x = t128 & 31;
            int ylocal = (t128 >> 5) * 10;   // 0,10,20,30
            int halfsel = tid >> 7;
            int vox = slice * HW_ + (ty0 + it * YIT + ylocal) * W_ + (tx0 + x);
            float v[20];
#define HCONV10(DST)                                                   \
            DST[0] = convs<0>(v); DST[1] = convs<1>(v);                \
            DST[2] = convs<2>(v); DST[3] = convs<3>(v);                \
            DST[4] = convs<4>(v); DST[5] = convs<5>(v);                \
            DST[6] = convs<6>(v); DST[7] = convs<7>(v);                \
            DST[8] = convs<8>(v); DST[9] = convs<9>(v);
            if (halfsel == 0) {
                float m1[10];
#pragma unroll
                for (int t = 0; t < 20; t++) v[t] = mid[0][ylocal + t][x];
                HCONV10(m1)
#pragma unroll
                for (int t = 0; t < 20; t++) v[t] = mid[1][ylocal + t][x];
#pragma unroll
                for (int u = 0; u < 10; u++) {
                    float m2 = u == 0 ? convs<0>(v) : u == 1 ? convs<1>(v)
                             : u == 2 ? convs<2>(v) : u == 3 ? convs<3>(v)
                             : u == 4 ? convs<4>(v) : u == 5 ? convs<5>(v)
                             : u == 6 ? convs<6>(v) : u == 7 ? convs<7>(v)
                             : u == 8 ? convs<8>(v) : convs<9>(v);
                    gA[vox + u * W_] = __floats2half2_rn(m1[u], m2);
                }
            } else {
                float e1[10];
#pragma unroll
                for (int t = 0; t < 20; t++) v[t] = mid[2][ylocal + t][x];
                HCONV10(e1)
#pragma unroll
                for (int t = 0; t < 20; t++) v[t] = mid[3][ylocal + t][x];
#pragma unroll
                for (int u = 0; u < 10; u++) {
                    float e2 = u == 0 ? convs<0>(v) : u == 1 ? convs<1>(v)
                             : u == 2 ? convs<2>(v) : u == 3 ? convs<3>(v)
                             : u == 4 ? convs<4>(v) : u == 5 ? convs<5>(v)
                             : u == 6 ? convs<6>(v) : u == 7 ? convs<7>(v)
                             : u == 8 ? convs<8>(v) : convs<9>(v);
                    gB[vox + u * W_] = __floats2half2_rn(e1[u], e2);
                }
#pragma unroll
                for (int t = 0; t < 20; t++) v[t] = mid[4][ylocal + t][x];
                HCONV10(e1)
#pragma unroll
                for (int u = 0; u < 10; u++)
                    gC[vox + u * W_] = __float2half_rn(e1[u]);
            }
#undef HCONV10
        }
    }
}

// ---------------------------------------------------------------------------
// Pass B (exact R15): D-conv via 13-deep rotating ring, D-split x2 (32 steps
// per half-column). Slot s holds real plane p with (p - dlo) mod 13 == s.
// No occupancy cap (a reg cap spills the ring — R14 lesson).
// ONLY change vs R15: last-finishing block emits the loss (counter) instead
// of a separate final_kernel launch.
// ---------------------------------------------------------------------------
template <int J>
__device__ __forceinline__ float conv13(const float (&r)[13]) {
    float s = r[(J + 8) % 13] * GW0;
#pragma unroll
    for (int k = 1; k < 11; k++) s = fmaf(r[(J + 8 + k) % 13], gw(k), s);
    return s;
}

template <int J>
__device__ __forceinline__ void stepJ(
    float (&a)[13], float (&b)[13], float (&c11)[13],
    float (&c22)[13], float (&c12)[13],
    const __half2* __restrict__ tA, const __half2* __restrict__ tB,
    const __half* __restrict__ tC,
    int o, float& acc, bool ld) {
    float mu1 = conv13<J>(a);
    float mu2 = conv13<J>(b);
    float e11 = conv13<J>(c11);
    float e22 = conv13<J>(c22);
    float e12 = conv13<J>(c12);

    float mu1sq = mu1 * mu1;
    float mu2sq = mu2 * mu2;
    float mu12 = mu1 * mu2;
    float s11 = e11 - mu1sq;
    float s22 = e22 - mu2sq;
    float s12 = e12 - mu12;

    float num = (2.f * mu12 + SSIM_C1) * (2.f * s12 + SSIM_C2);
    float den = (mu1sq + mu2sq + SSIM_C1) * (s11 + s22 + SSIM_C2);
    acc += __fdividef(num, den);

    constexpr int RS = (J + 8) % 13;
    if (ld) {
        float2 ab = __half22float2(tA[o]);
        float2 ee = __half22float2(tB[o]);
        a[RS] = ab.x; b[RS] = ab.y;
        c11[RS] = ee.x; c22[RS] = ee.y;
        c12[RS] = __half2float(tC[o]);
    } else {
        a[RS] = 0.f; b[RS] = 0.f; c11[RS] = 0.f; c22[RS] = 0.f; c12[RS] = 0.f;
    }
}

__global__ void __launch_bounds__(160) passB_kernel(float* __restrict__ out) {
    const int bid = blockIdx.x;          // ((bc*H + y) << 1) | dh
    const int dh = bid & 1;
    const int rest = bid >> 1;           // bc*H + y
    const int y = rest % H_;
    const int bc = rest / H_;
    const int c = bc % C_;
    const int x = threadIdx.x;           // 0..159
    const int dlo = dh << 5;             // 0 or 32

    const int colbase = (bc * D_ + dlo) * HW_ + y * W_ + x;
    const __half2* tA = gA + colbase;
    const __half2* tB = gB + colbase;
    const __half*  tC = gC + colbase;

    float a[13], b[13], c11[13], c22[13], c12[13];
    // Preload under slot = (plane - dlo) mod 13:
    //   slots 0..7  <- planes dlo .. dlo+7
    //   slots 8..12 <- planes dlo-5 .. dlo-1   (zero when plane < 0, i.e. dh==0)
#pragma unroll
    for (int k = 0; k < 13; k++) {
        const int rel = (k < 8) ? k : (k - 13);   // -5..7
        const int o = rel * HW_;
        bool ok = (dlo + rel) >= 0;               // upper bound always ok
        if (ok) {
            float2 ab = __half22float2(tA[o]);
            float2 ee = __half22float2(tB[o]);
            a[k] = ab.x; b[k] = ab.y;
            c11[k] = ee.x; c22[k] = ee.y;
            c12[k] = __half2float(tC[o]);
        } else {
            a[k] = 0.f; b[k] = 0.f; c11[k] = 0.f; c22[k] = 0.f; c12[k] = 0.f;
        }
    }

    float acc = 0.f;
    int o = 8 * HW_;  // step d_rel refills plane dlo + d_rel + 8

    // Refill validity: dlo + d_rel + 8 <= 63  <=>  d_rel <= 55 - dlo.
#define STEP(J, LD) stepJ<J>(a, b, c11, c22, c12, tA, tB, tC, o, acc, (LD)); o += HW_;

    // d_rel = 0..25 : two rotations of 13.
#pragma unroll 1
    for (int r = 0; r < 2; r++) {
        int dbase = r * 13;
        STEP(0,  dbase + 0  <= 55 - dlo)
        STEP(1,  dbase + 1  <= 55 - dlo)
        STEP(2,  dbase + 2  <= 55 - dlo)
        STEP(3,  dbase + 3  <= 55 - dlo)
        STEP(4,  dbase + 4  <= 55 - dlo)
        STEP(5,  dbase + 5  <= 55 - dlo)
        STEP(6,  dbase + 6  <= 55 - dlo)
        STEP(7,  dbase + 7  <= 55 - dlo)
        STEP(8,  dbase + 8  <= 55 - dlo)
        STEP(9,  dbase + 9  <= 55 - dlo)
        STEP(10, dbase + 10 <= 55 - dlo)
        STEP(11, dbase + 11 <= 55 - dlo)
        STEP(12, dbase + 12 <= 55 - dlo)
    }
    // d_rel = 26..31 (J = 0..5): load valid only for dh == 0 (planes 34..39).
    {
        const bool lt = (dlo == 0);
        STEP(0, lt) STEP(1, lt) STEP(2, lt)
        STEP(3, lt) STEP(4, lt) STEP(5, lt)
    }
#undef STEP

    __shared__ float red[5];
    __shared__ bool s_last;
#pragma unroll
    for (int off = 16; off > 0; off >>= 1)
        acc += __shfl_down_sync(0xffffffffu, acc, off);
    if ((threadIdx.x & 31) == 0) red[threadIdx.x >> 5] = acc;
    __syncthreads();
    if (threadIdx.x == 0) {
        float s = red[0] + red[1] + red[2] + red[3] + red[4];
        atomicAdd(&g_acc[c], s);
        __threadfence();
        unsigned int t = atomicAdd(&g_done, 1u);
        s_last = (t == (unsigned)(NBLK_B - 1));
    }
    __syncthreads();
    // Last block: emit the loss and reset state for the next graph replay
    // (deterministic: exactly one block takes this path, after all sums land).
    if (s_last) {
        if (threadIdx.x < C_) {
            float s = *((volatile float*)&g_acc[threadIdx.x]);
            out[threadIdx.x] = 1.f - s * (1.f / (float)NVOX_PER_CH);
            g_acc[threadIdx.x] = 0.f;
        }
        if (threadIdx.x == 0) g_done = 0u;
    }
}

extern "C" void kernel_launch(void* const* d_in, const int* in_sizes, int n_in,
                              void* d_out, int out_size) {
    (void)in_sizes; (void)n_in; (void)out_size;
    const float* img1 = (const float*)d_in[0];
    const float* img2 = (const float*)d_in[1];
    float* out = (float*)d_out;

    dim3 gA_(W_ / TSX, H_ / (2 * YIT), NSLICE);  // (5, 2, 512)
    passA_kernel<<<gA_, 256>>>(img1, img2);
    passB_kernel<<<NBLK_B, 160>>>(out);
}